// round 1
// baseline (speedup 1.0000x reference)
#include <cuda_runtime.h>
#include <cuda_bf16.h>
#include <stdint.h>

#define B_     1024
#define NITEMS 50000
#define H1     600
#define H2     200
#define XB_LD  50048   // padded row stride for bf16 x

// ---------------- device scratch (no allocations allowed) ----------------
__device__ __nv_bfloat16 g_xb[(size_t)B_ * XB_LD];   // ~102 MB
__device__ float g_invn[B_];
__device__ float g_h1pre[B_ * H1];
__device__ float g_h1[B_ * H1];
__device__ float g_h2[B_ * H2];
__device__ float g_h3[B_ * H1];
__device__ float g_hsq[B_];
__device__ float g_esq[NITEMS];

// ---------------- helpers ----------------
__device__ __forceinline__ void mma_bf16(float* c, const uint32_t* a, const uint32_t* b) {
    asm volatile(
        "mma.sync.aligned.m16n8k16.row.col.f32.bf16.bf16.f32 "
        "{%0,%1,%2,%3},{%4,%5,%6,%7},{%8,%9},{%0,%1,%2,%3};\n"
        : "+f"(c[0]), "+f"(c[1]), "+f"(c[2]), "+f"(c[3])
        : "r"(a[0]), "r"(a[1]), "r"(a[2]), "r"(a[3]), "r"(b[0]), "r"(b[1]));
}

// ---------------- kernel 0: zero h1pre (split-K atomics accumulate into it) ----------------
__global__ void k_zero_h1pre() {
    int i = blockIdx.x * blockDim.x + threadIdx.x;
    if (i < B_ * H1) g_h1pre[i] = 0.0f;
}

// ---------------- kernel 1: row sumsq + fp32->bf16 convert of x ----------------
__global__ void k_norm_convert(const float* __restrict__ x) {
    int row = blockIdx.x;
    const float* xr = x + (size_t)row * NITEMS;
    __nv_bfloat16* xbr = g_xb + (size_t)row * XB_LD;
    float s = 0.0f;
    for (int c = threadIdx.x; c < NITEMS / 8; c += 256) {
        float4 f0 = *reinterpret_cast<const float4*>(xr + c * 8);
        float4 f1 = *reinterpret_cast<const float4*>(xr + c * 8 + 4);
        s += f0.x * f0.x + f0.y * f0.y + f0.z * f0.z + f0.w * f0.w;
        s += f1.x * f1.x + f1.y * f1.y + f1.z * f1.z + f1.w * f1.w;
        __nv_bfloat162 p[4];
        p[0] = __floats2bfloat162_rn(f0.x, f0.y);
        p[1] = __floats2bfloat162_rn(f0.z, f0.w);
        p[2] = __floats2bfloat162_rn(f1.x, f1.y);
        p[3] = __floats2bfloat162_rn(f1.z, f1.w);
        *reinterpret_cast<uint4*>(xbr + c * 8) = *reinterpret_cast<uint4*>(p);
    }
    __shared__ float red[256];
    red[threadIdx.x] = s;
    __syncthreads();
    for (int o = 128; o > 0; o >>= 1) {
        if (threadIdx.x < o) red[threadIdx.x] += red[threadIdx.x + o];
        __syncthreads();
    }
    if (threadIdx.x == 0) {
        float n = sqrtf(red[0]);
        g_invn[row] = 1.0f / fmaxf(n, 1e-12f);
    }
}

// ---------------- kernel 2: e_sq per item (fp32) ----------------
__global__ void k_esq(const float* __restrict__ E) {
    int row = blockIdx.x * 8 + (threadIdx.x >> 5);
    int lane = threadIdx.x & 31;
    const float* er = E + (size_t)row * H1;
    float s = 0.0f;
    for (int k = lane * 2; k < H1; k += 64) {
        float2 v = *reinterpret_cast<const float2*>(er + k);
        s += v.x * v.x + v.y * v.y;
    }
    #pragma unroll
    for (int o = 16; o > 0; o >>= 1) s += __shfl_xor_sync(0xffffffffu, s, o);
    if (lane == 0) g_esq[row] = s;
}

// ---------------- kernel 3: GEMM1  h1pre += x_bf16 @ W1  (split-K, atomics) ----------------
// grid (40, 25): blockIdx.x = tile (mtile = x&7, ntile = x>>3), blockIdx.y = ksplit
__global__ __launch_bounds__(256) void k_gemm1(const float* __restrict__ W1) {
    const int tid = threadIdx.x;
    const int m0 = (blockIdx.x & 7) * 128;
    const int n0 = (blockIdx.x >> 3) * 128;
    const int k0 = blockIdx.y * 2048;

    __shared__ __nv_bfloat16 As[128 * 40];
    __shared__ __nv_bfloat16 Bs[128 * 40];

    const int lane = tid & 31, warp = tid >> 5;
    const int wm = (warp & 3) * 32, wn = (warp >> 2) * 64;
    const int gid = lane >> 2, tig = lane & 3;

    float acc[2][8][4];
    #pragma unroll
    for (int im = 0; im < 2; im++)
        #pragma unroll
        for (int in = 0; in < 8; in++)
            #pragma unroll
            for (int j = 0; j < 4; j++) acc[im][in][j] = 0.0f;

    for (int kg = k0; kg < k0 + 2048; kg += 32) {
        // A tile: 128m x 32k bf16 from g_xb
        #pragma unroll
        for (int i = 0; i < 2; i++) {
            int idx = tid + i * 256;
            int m = idx >> 2, kc = idx & 3;
            int gk = kg + kc * 8;
            uint4 v = make_uint4(0u, 0u, 0u, 0u);
            if (gk < NITEMS)
                v = *reinterpret_cast<const uint4*>(&g_xb[(size_t)(m0 + m) * XB_LD + gk]);
            *reinterpret_cast<uint4*>(&As[m * 40 + kc * 8]) = v;
        }
        // B tile: Bs[n][k] = bf16(W1[k][n])  (transpose + convert)
        #pragma unroll
        for (int i = 0; i < 4; i++) {
            int idx = tid + i * 256;
            int kr = idx >> 5, nc = idx & 31;
            int gk = kg + kr;
            int n = n0 + nc * 4;
            float4 w = make_float4(0.f, 0.f, 0.f, 0.f);
            if (gk < NITEMS && n < H1)
                w = *reinterpret_cast<const float4*>(&W1[(size_t)gk * H1 + n]);
            Bs[(nc * 4 + 0) * 40 + kr] = __float2bfloat16_rn(w.x);
            Bs[(nc * 4 + 1) * 40 + kr] = __float2bfloat16_rn(w.y);
            Bs[(nc * 4 + 2) * 40 + kr] = __float2bfloat16_rn(w.z);
            Bs[(nc * 4 + 3) * 40 + kr] = __float2bfloat16_rn(w.w);
        }
        __syncthreads();
        #pragma unroll
        for (int kk = 0; kk < 32; kk += 16) {
            uint32_t a[2][4], b[8][2];
            #pragma unroll
            for (int im = 0; im < 2; im++) {
                const __nv_bfloat16* base = &As[(wm + im * 16 + gid) * 40 + kk + tig * 2];
                a[im][0] = *reinterpret_cast<const uint32_t*>(base);
                a[im][1] = *reinterpret_cast<const uint32_t*>(base + 8 * 40);
                a[im][2] = *reinterpret_cast<const uint32_t*>(base + 8);
                a[im][3] = *reinterpret_cast<const uint32_t*>(base + 8 * 40 + 8);
            }
            #pragma unroll
            for (int in = 0; in < 8; in++) {
                const __nv_bfloat16* base = &Bs[(wn + in * 8 + gid) * 40 + kk + tig * 2];
                b[in][0] = *reinterpret_cast<const uint32_t*>(base);
                b[in][1] = *reinterpret_cast<const uint32_t*>(base + 8);
            }
            #pragma unroll
            for (int im = 0; im < 2; im++)
                #pragma unroll
                for (int in = 0; in < 8; in++)
                    mma_bf16(acc[im][in], a[im], b[in]);
        }
        __syncthreads();
    }
    // epilogue: accumulate split-K partials
    #pragma unroll
    for (int im = 0; im < 2; im++) {
        int r = m0 + wm + im * 16 + gid;
        #pragma unroll
        for (int in = 0; in < 8; in++) {
            int c = n0 + wn + in * 8 + tig * 2;
            if (c < H1) {
                atomicAdd(&g_h1pre[r * H1 + c],       acc[im][in][0]);
                atomicAdd(&g_h1pre[r * H1 + c + 1],   acc[im][in][1]);
                atomicAdd(&g_h1pre[(r + 8) * H1 + c],     acc[im][in][2]);
                atomicAdd(&g_h1pre[(r + 8) * H1 + c + 1], acc[im][in][3]);
            }
        }
    }
}

// ---------------- kernel 4: h1 = tanh(invn[m]*h1pre + b1[n]) ----------------
__global__ void k_act1(const float* __restrict__ b1) {
    int i = blockIdx.x * blockDim.x + threadIdx.x;
    if (i >= B_ * H1) return;
    int m = i / H1, n = i - m * H1;
    g_h1[i] = tanhf(g_h1pre[i] * g_invn[m] + b1[n]);
}

// ---------------- kernel 5: h2 = tanh(h1 @ W2 + b2), K=600, N=200 ----------------
__global__ void k_mlp2(const float* __restrict__ W, const float* __restrict__ bias) {
    int m = blockIdx.x;
    __shared__ float a[H1];
    for (int k = threadIdx.x; k < H1; k += 256) a[k] = g_h1[m * H1 + k];
    __syncthreads();
    int n = threadIdx.x;
    if (n < H2) {
        float acc0 = 0.f, acc1 = 0.f;
        #pragma unroll 4
        for (int k = 0; k < H1; k += 2) {
            acc0 = fmaf(a[k],     W[k * H2 + n],       acc0);
            acc1 = fmaf(a[k + 1], W[(k + 1) * H2 + n], acc1);
        }
        g_h2[m * H2 + n] = tanhf(acc0 + acc1 + bias[n]);
    }
}

// ---------------- kernel 6: h3 = tanh(h2 @ W3 + b3), K=200, N=600; also hsq ----------------
__global__ void k_mlp3(const float* __restrict__ W, const float* __restrict__ bias) {
    int m = blockIdx.x;
    __shared__ float a[H2];
    __shared__ float red[256];
    for (int k = threadIdx.x; k < H2; k += 256) a[k] = g_h2[m * H2 + k];
    __syncthreads();
    float ssq = 0.f;
    for (int n = threadIdx.x; n < H1; n += 256) {
        float acc0 = 0.f, acc1 = 0.f;
        #pragma unroll 4
        for (int k = 0; k < H2; k += 2) {
            acc0 = fmaf(a[k],     W[k * H1 + n],       acc0);
            acc1 = fmaf(a[k + 1], W[(k + 1) * H1 + n], acc1);
        }
        float h = tanhf(acc0 + acc1 + bias[n]);
        g_h3[m * H1 + n] = h;
        ssq += h * h;
    }
    red[threadIdx.x] = ssq;
    __syncthreads();
    for (int o = 128; o > 0; o >>= 1) {
        if (threadIdx.x < o) red[threadIdx.x] += red[threadIdx.x + o];
        __syncthreads();
    }
    if (threadIdx.x == 0) g_hsq[m] = red[0];
}

// ---------------- kernel 7: GEMM2  out = hsq[m] + esq[n] - 2*(h3 @ E^T) ----------------
// grid (8, 391): x = mtile (fast -> E-tile L2 reuse across mtiles), y = ntile
__global__ __launch_bounds__(256) void k_gemm2(const float* __restrict__ E,
                                               float* __restrict__ out) {
    const int tid = threadIdx.x;
    const int m0 = blockIdx.x * 128;
    const int n0 = blockIdx.y * 128;

    __shared__ __nv_bfloat16 As[128 * 40];
    __shared__ __nv_bfloat16 Bs[128 * 40];

    const int lane = tid & 31, warp = tid >> 5;
    const int wm = (warp & 3) * 32, wn = (warp >> 2) * 64;
    const int gid = lane >> 2, tig = lane & 3;

    float acc[2][8][4];
    #pragma unroll
    for (int im = 0; im < 2; im++)
        #pragma unroll
        for (int in = 0; in < 8; in++)
            #pragma unroll
            for (int j = 0; j < 4; j++) acc[im][in][j] = 0.0f;

    for (int kg = 0; kg < H1; kg += 32) {
        // A tile from h3 (fp32 -> bf16)
        #pragma unroll
        for (int i = 0; i < 4; i++) {
            int idx = tid + i * 256;
            int m = idx >> 3, kc = idx & 7;
            int gk = kg + kc * 4;
            float4 v = make_float4(0.f, 0.f, 0.f, 0.f);
            if (gk < H1)
                v = *reinterpret_cast<const float4*>(&g_h3[(size_t)(m0 + m) * H1 + gk]);
            *reinterpret_cast<__nv_bfloat162*>(&As[m * 40 + kc * 4])     = __floats2bfloat162_rn(v.x, v.y);
            *reinterpret_cast<__nv_bfloat162*>(&As[m * 40 + kc * 4 + 2]) = __floats2bfloat162_rn(v.z, v.w);
        }
        // B tile: Bs[n][k] = bf16(E[n][k])  (E rows are already k-contiguous)
        #pragma unroll
        for (int i = 0; i < 4; i++) {
            int idx = tid + i * 256;
            int n = idx >> 3, kc = idx & 7;
            int gk = kg + kc * 4;
            int gn = n0 + n;
            float4 v = make_float4(0.f, 0.f, 0.f, 0.f);
            if (gn < NITEMS && gk < H1)
                v = *reinterpret_cast<const float4*>(&E[(size_t)gn * H1 + gk]);
            *reinterpret_cast<__nv_bfloat162*>(&Bs[n * 40 + kc * 4])     = __floats2bfloat162_rn(v.x, v.y);
            *reinterpret_cast<__nv_bfloat162*>(&Bs[n * 40 + kc * 4 + 2]) = __floats2bfloat162_rn(v.z, v.w);
        }
        __syncthreads();
        #pragma unroll
        for (int kk = 0; kk < 32; kk += 16) {
            uint32_t a[2][4], b[8][2];
            #pragma unroll
            for (int im = 0; im < 2; im++) {
                const __nv_bfloat16* base = &As[(wm + im * 16 + gid) * 40 + kk + tig * 2];
                a[im][0] = *reinterpret_cast<const uint32_t*>(base);
                a[im][1] = *reinterpret_cast<const uint32_t*>(base + 8 * 40);
                a[im][2] = *reinterpret_cast<const uint32_t*>(base + 8);
                a[im][3] = *reinterpret_cast<const uint32_t*>(base + 8 * 40 + 8);
            }
            #pragma unroll
            for (int in = 0; in < 8; in++) {
                const __nv_bfloat16* base = &Bs[(wn + in * 8 + gid) * 40 + kk + tig * 2];
                b[in][0] = *reinterpret_cast<const uint32_t*>(base);
                b[in][1] = *reinterpret_cast<const uint32_t*>(base + 8);
            }
            #pragma unroll
            for (int im = 0; im < 2; im++)
                #pragma unroll
                for (int in = 0; in < 8; in++)
                    mma_bf16(acc[im][in], a[im], b[in]);
        }
        __syncthreads();
    }
    // epilogue: dist = hsq[m] + esq[n] - 2*acc, streaming stores
    #pragma unroll
    for (int im = 0; im < 2; im++) {
        int r = m0 + wm + im * 16 + gid;
        float hs0 = __ldg(&g_hsq[r]);
        float hs1 = __ldg(&g_hsq[r + 8]);
        #pragma unroll
        for (int in = 0; in < 8; in++) {
            int c = n0 + wn + in * 8 + tig * 2;
            if (c < NITEMS) {
                float e0 = __ldg(&g_esq[c]);
                float e1 = __ldg(&g_esq[c + 1]);
                float2 o0, o1;
                o0.x = hs0 + e0 - 2.0f * acc[im][in][0];
                o0.y = hs0 + e1 - 2.0f * acc[im][in][1];
                o1.x = hs1 + e0 - 2.0f * acc[im][in][2];
                o1.y = hs1 + e1 - 2.0f * acc[im][in][3];
                __stcs(reinterpret_cast<float2*>(&out[(size_t)r * NITEMS + c]), o0);
                __stcs(reinterpret_cast<float2*>(&out[(size_t)(r + 8) * NITEMS + c]), o1);
            }
        }
    }
}

// ---------------- launch ----------------
extern "C" void kernel_launch(void* const* d_in, const int* in_sizes, int n_in,
                              void* d_out, int out_size) {
    const float* x  = (const float*)d_in[0];
    const float* W1 = (const float*)d_in[1];
    const float* b1 = (const float*)d_in[2];
    const float* W2 = (const float*)d_in[3];
    const float* b2 = (const float*)d_in[4];
    const float* W3 = (const float*)d_in[5];
    const float* b3 = (const float*)d_in[6];
    const float* E  = (const float*)d_in[7];
    float* out = (float*)d_out;

    k_zero_h1pre<<<(B_ * H1 + 255) / 256, 256>>>();
    k_norm_convert<<<B_, 256>>>(x);
    k_esq<<<NITEMS / 8, 256>>>(E);
    k_gemm1<<<dim3(40, 25), 256>>>(W1);
    k_act1<<<(B_ * H1 + 255) / 256, 256>>>(b1);
    k_mlp2<<<B_, 256>>>(W2, b2);
    k_mlp3<<<B_, 256>>>(W3, b3);
    k_gemm2<<<dim3(8, 391), 256>>>(E, out);
}

// round 2
// speedup vs baseline: 1.7645x; 1.7645x over previous
#include <cuda_runtime.h>
#include <cuda_bf16.h>
#include <stdint.h>

#define B_     1024
#define NITEMS 50000
#define H1     600
#define H2     200
#define XB_LD  50048   // padded bf16 row stride for x and W1^T (k dim)
#define EB_LD  608     // padded bf16 row stride for E / h3 (k dim)

// ---------------- device scratch (static => zero-init; pads never written) ----------------
__device__ __nv_bfloat16 g_xb [(size_t)B_ * XB_LD];        // ~102 MB, x in bf16
__device__ __nv_bfloat16 g_w1t[(size_t)640 * XB_LD];       // ~64 MB, W1^T bf16 [n][k]
__device__ __nv_bfloat16 g_eb [(size_t)50048 * EB_LD];     // ~61 MB, E bf16 [n][k]
__device__ __nv_bfloat16 g_h3b[(size_t)B_ * EB_LD];        // h3 bf16 [m][k]
__device__ float g_invn[B_];
__device__ float g_h1pre[B_ * H1];
__device__ float g_h1[B_ * H1];
__device__ float g_h2[B_ * H2];
__device__ float g_hsq[B_];
__device__ float g_esq[NITEMS];

// ---------------- asm helpers ----------------
__device__ __forceinline__ void mma_bf16(float* c, const uint32_t* a, const uint32_t* b) {
    asm volatile(
        "mma.sync.aligned.m16n8k16.row.col.f32.bf16.bf16.f32 "
        "{%0,%1,%2,%3},{%4,%5,%6,%7},{%8,%9},{%0,%1,%2,%3};\n"
        : "+f"(c[0]), "+f"(c[1]), "+f"(c[2]), "+f"(c[3])
        : "r"(a[0]), "r"(a[1]), "r"(a[2]), "r"(a[3]), "r"(b[0]), "r"(b[1]));
}
__device__ __forceinline__ uint32_t smem_u32(const void* p) {
    return (uint32_t)__cvta_generic_to_shared(p);
}
__device__ __forceinline__ void cp16(uint32_t dst, const void* src) {
    asm volatile("cp.async.cg.shared.global [%0], [%1], 16;\n" :: "r"(dst), "l"(src));
}
__device__ __forceinline__ void cp_commit() { asm volatile("cp.async.commit_group;\n"); }
template<int N> __device__ __forceinline__ void cp_wait() {
    asm volatile("cp.async.wait_group %0;\n" :: "n"(N));
}
__device__ __forceinline__ void ldsm4(uint32_t& r0, uint32_t& r1, uint32_t& r2, uint32_t& r3,
                                      uint32_t addr) {
    asm volatile("ldmatrix.sync.aligned.m8n8.x4.shared.b16 {%0,%1,%2,%3}, [%4];\n"
                 : "=r"(r0), "=r"(r1), "=r"(r2), "=r"(r3) : "r"(addr));
}

// ---------------- shared GEMM building blocks ----------------
// Tile: BM=128, BN=128, BK=32. smem rows padded to 40 halfs (80B) -> conflict-free LDSM.
__device__ __forceinline__ void issue_stage(
    __nv_bfloat16* As, __nv_bfloat16* Bs,
    const __nv_bfloat16* __restrict__ A, size_t lda, int m0,
    const __nv_bfloat16* __restrict__ B, size_t ldb, int n0,
    int kg, int tid)
{
    #pragma unroll
    for (int i = 0; i < 2; i++) {
        int c = tid + i * 256;
        int row = c >> 2, kc = c & 3;
        cp16(smem_u32(As + row * 40 + kc * 8), A + (size_t)(m0 + row) * lda + kg + kc * 8);
    }
    #pragma unroll
    for (int i = 0; i < 2; i++) {
        int c = tid + i * 256;
        int row = c >> 2, kc = c & 3;
        cp16(smem_u32(Bs + row * 40 + kc * 8), B + (size_t)(n0 + row) * ldb + kg + kc * 8);
    }
}

__device__ __forceinline__ void compute_stage(
    const __nv_bfloat16* As, const __nv_bfloat16* Bs,
    int wm, int wn, int lane, float acc[2][8][4])
{
    #pragma unroll
    for (int kk = 0; kk < 32; kk += 16) {
        uint32_t a[2][4];
        #pragma unroll
        for (int im = 0; im < 2; im++) {
            uint32_t addr = smem_u32(As + (wm + im * 16 + (lane & 15)) * 40
                                        + kk + ((lane >> 4) << 3));
            ldsm4(a[im][0], a[im][1], a[im][2], a[im][3], addr);
        }
        uint32_t b[8][2];
        #pragma unroll
        for (int ip = 0; ip < 4; ip++) {
            uint32_t addr = smem_u32(Bs + (wn + ip * 16 + ((lane >> 4) << 3) + (lane & 7)) * 40
                                        + kk + (((lane >> 3) & 1) << 3));
            uint32_t r0, r1, r2, r3;
            ldsm4(r0, r1, r2, r3, addr);
            b[ip * 2][0] = r0; b[ip * 2][1] = r1;
            b[ip * 2 + 1][0] = r2; b[ip * 2 + 1][1] = r3;
        }
        #pragma unroll
        for (int im = 0; im < 2; im++)
            #pragma unroll
            for (int in = 0; in < 8; in++)
                mma_bf16(acc[im][in], a[im], b[in]);
    }
}

// ---------------- kernel: zero h1pre ----------------
__global__ void k_zero_h1pre() {
    int i = blockIdx.x * blockDim.x + threadIdx.x;
    if (i < B_ * H1) g_h1pre[i] = 0.0f;
}

// ---------------- kernel: row sumsq + fp32->bf16 convert of x ----------------
__global__ void k_norm_convert(const float* __restrict__ x) {
    int row = blockIdx.x;
    const float* xr = x + (size_t)row * NITEMS;
    __nv_bfloat16* xbr = g_xb + (size_t)row * XB_LD;
    float s = 0.0f;
    for (int c = threadIdx.x; c < NITEMS / 8; c += 256) {
        float4 f0 = *reinterpret_cast<const float4*>(xr + c * 8);
        float4 f1 = *reinterpret_cast<const float4*>(xr + c * 8 + 4);
        s += f0.x * f0.x + f0.y * f0.y + f0.z * f0.z + f0.w * f0.w;
        s += f1.x * f1.x + f1.y * f1.y + f1.z * f1.z + f1.w * f1.w;
        __nv_bfloat162 p[4];
        p[0] = __floats2bfloat162_rn(f0.x, f0.y);
        p[1] = __floats2bfloat162_rn(f0.z, f0.w);
        p[2] = __floats2bfloat162_rn(f1.x, f1.y);
        p[3] = __floats2bfloat162_rn(f1.z, f1.w);
        *reinterpret_cast<uint4*>(xbr + c * 8) = *reinterpret_cast<uint4*>(p);
    }
    __shared__ float red[256];
    red[threadIdx.x] = s;
    __syncthreads();
    for (int o = 128; o > 0; o >>= 1) {
        if (threadIdx.x < o) red[threadIdx.x] += red[threadIdx.x + o];
        __syncthreads();
    }
    if (threadIdx.x == 0) {
        float n = sqrtf(red[0]);
        g_invn[row] = 1.0f / fmaxf(n, 1e-12f);
    }
}

// ---------------- kernel: W1 [k][n] fp32 -> g_w1t [n][k] bf16 (tiled transpose) ----------------
__global__ void k_prep_w1t(const float* __restrict__ W1) {
    __shared__ float t[32][33];
    int k0 = blockIdx.x * 32, n0 = blockIdx.y * 32;
    int tr = threadIdx.x >> 5, tc = threadIdx.x & 31;
    #pragma unroll
    for (int i = 0; i < 4; i++) {
        int kr = k0 + i * 8 + tr;
        float v = 0.0f;
        if (kr < NITEMS && n0 + tc < H1) v = W1[(size_t)kr * H1 + n0 + tc];
        t[i * 8 + tr][tc] = v;
    }
    __syncthreads();
    #pragma unroll
    for (int i = 0; i < 4; i++) {
        int nr = n0 + i * 8 + tr;
        g_w1t[(size_t)nr * XB_LD + k0 + tc] = __float2bfloat16_rn(t[tc][i * 8 + tr]);
    }
}

// ---------------- kernel: E fp32 -> g_eb bf16 (same layout, padded rows) ----------------
__global__ void k_prep_eb(const float* __restrict__ E) {
    int idx = blockIdx.x * 256 + threadIdx.x;   // over 50000 * 150 float4s
    if (idx >= NITEMS * (H1 / 4)) return;
    int row = idx / (H1 / 4), c = idx - row * (H1 / 4);
    float4 v = *reinterpret_cast<const float4*>(E + (size_t)row * H1 + c * 4);
    __nv_bfloat162 p0 = __floats2bfloat162_rn(v.x, v.y);
    __nv_bfloat162 p1 = __floats2bfloat162_rn(v.z, v.w);
    uint2 u;
    u.x = *reinterpret_cast<uint32_t*>(&p0);
    u.y = *reinterpret_cast<uint32_t*>(&p1);
    *reinterpret_cast<uint2*>(&g_eb[(size_t)row * EB_LD + c * 4]) = u;
}

// ---------------- kernel: e_sq per item (fp32) ----------------
__global__ void k_esq(const float* __restrict__ E) {
    int row = blockIdx.x * 8 + (threadIdx.x >> 5);
    int lane = threadIdx.x & 31;
    const float* er = E + (size_t)row * H1;
    float s = 0.0f;
    for (int k = lane * 2; k < H1; k += 64) {
        float2 v = *reinterpret_cast<const float2*>(er + k);
        s += v.x * v.x + v.y * v.y;
    }
    #pragma unroll
    for (int o = 16; o > 0; o >>= 1) s += __shfl_xor_sync(0xffffffffu, s, o);
    if (lane == 0) g_esq[row] = s;
}

// ---------------- GEMM1: h1pre += x_bf16 @ W1 (split-K, atomics) ----------------
// grid (40, 23): x = tile (m = x&7, n = x>>3), y = ksplit of 68 k-tiles (68*32=2176)
__global__ __launch_bounds__(256, 2) void k_gemm1() {
    const int tid = threadIdx.x;
    const int m0 = (blockIdx.x & 7) * 128;
    const int n0 = (blockIdx.x >> 3) * 128;
    const int kg0 = blockIdx.y * 68 * 32;

    __shared__ __nv_bfloat16 As[2][128 * 40];
    __shared__ __nv_bfloat16 Bs[2][128 * 40];

    const int lane = tid & 31, warp = tid >> 5;
    const int wm = (warp & 3) * 32, wn = (warp >> 2) * 64;
    const int gid = lane >> 2, tig = lane & 3;

    float acc[2][8][4];
    #pragma unroll
    for (int im = 0; im < 2; im++)
        #pragma unroll
        for (int in = 0; in < 8; in++)
            #pragma unroll
            for (int j = 0; j < 4; j++) acc[im][in][j] = 0.0f;

    issue_stage(As[0], Bs[0], g_xb, XB_LD, m0, g_w1t, XB_LD, n0, kg0, tid);
    cp_commit();
    const int NT = 68;
    for (int kt = 0; kt < NT; kt++) {
        if (kt + 1 < NT)
            issue_stage(As[(kt + 1) & 1], Bs[(kt + 1) & 1],
                        g_xb, XB_LD, m0, g_w1t, XB_LD, n0, kg0 + (kt + 1) * 32, tid);
        cp_commit();
        cp_wait<1>();
        __syncthreads();
        compute_stage(As[kt & 1], Bs[kt & 1], wm, wn, lane, acc);
        __syncthreads();
    }
    #pragma unroll
    for (int im = 0; im < 2; im++) {
        int r = m0 + wm + im * 16 + gid;
        #pragma unroll
        for (int in = 0; in < 8; in++) {
            int c = n0 + wn + in * 8 + tig * 2;
            if (c < H1) {
                atomicAdd(&g_h1pre[r * H1 + c],           acc[im][in][0]);
                atomicAdd(&g_h1pre[r * H1 + c + 1],       acc[im][in][1]);
                atomicAdd(&g_h1pre[(r + 8) * H1 + c],     acc[im][in][2]);
                atomicAdd(&g_h1pre[(r + 8) * H1 + c + 1], acc[im][in][3]);
            }
        }
    }
}

// ---------------- kernel: h1 = tanh(invn[m]*h1pre + b1[n]) ----------------
__global__ void k_act1(const float* __restrict__ b1) {
    int i = blockIdx.x * blockDim.x + threadIdx.x;
    if (i >= B_ * H1) return;
    int m = i / H1, n = i - m * H1;
    g_h1[i] = tanhf(g_h1pre[i] * g_invn[m] + b1[n]);
}

// ---------------- kernel: h2 = tanh(h1 @ W2 + b2) ----------------
__global__ void k_mlp2(const float* __restrict__ W, const float* __restrict__ bias) {
    int m = blockIdx.x;
    __shared__ float a[H1];
    for (int k = threadIdx.x; k < H1; k += 256) a[k] = g_h1[m * H1 + k];
    __syncthreads();
    int n = threadIdx.x;
    if (n < H2) {
        float acc0 = 0.f, acc1 = 0.f;
        #pragma unroll 4
        for (int k = 0; k < H1; k += 2) {
            acc0 = fmaf(a[k],     W[k * H2 + n],       acc0);
            acc1 = fmaf(a[k + 1], W[(k + 1) * H2 + n], acc1);
        }
        g_h2[m * H2 + n] = tanhf(acc0 + acc1 + bias[n]);
    }
}

// ---------------- kernel: h3 = tanh(h2 @ W3 + b3) -> bf16; also hsq ----------------
__global__ void k_mlp3(const float* __restrict__ W, const float* __restrict__ bias) {
    int m = blockIdx.x;
    __shared__ float a[H2];
    __shared__ float red[256];
    for (int k = threadIdx.x; k < H2; k += 256) a[k] = g_h2[m * H2 + k];
    __syncthreads();
    float ssq = 0.f;
    for (int n = threadIdx.x; n < H1; n += 256) {
        float acc0 = 0.f, acc1 = 0.f;
        #pragma unroll 4
        for (int k = 0; k < H2; k += 2) {
            acc0 = fmaf(a[k],     W[k * H1 + n],       acc0);
            acc1 = fmaf(a[k + 1], W[(k + 1) * H1 + n], acc1);
        }
        float h = tanhf(acc0 + acc1 + bias[n]);
        g_h3b[(size_t)m * EB_LD + n] = __float2bfloat16_rn(h);
        ssq += h * h;
    }
    red[threadIdx.x] = ssq;
    __syncthreads();
    for (int o = 128; o > 0; o >>= 1) {
        if (threadIdx.x < o) red[threadIdx.x] += red[threadIdx.x + o];
        __syncthreads();
    }
    if (threadIdx.x == 0) g_hsq[m] = red[0];
}

// ---------------- GEMM2: out = hsq[m] + esq[n] - 2*(h3 @ E^T) ----------------
// grid (8, 391): x = mtile (fast -> E-panel L2 reuse), y = ntile. K = 608 (19 tiles).
__global__ __launch_bounds__(256, 2) void k_gemm2(float* __restrict__ out) {
    const int tid = threadIdx.x;
    const int m0 = blockIdx.x * 128;
    const int n0 = blockIdx.y * 128;

    __shared__ __nv_bfloat16 As[2][128 * 40];
    __shared__ __nv_bfloat16 Bs[2][128 * 40];

    const int lane = tid & 31, warp = tid >> 5;
    const int wm = (warp & 3) * 32, wn = (warp >> 2) * 64;
    const int gid = lane >> 2, tig = lane & 3;

    float acc[2][8][4];
    #pragma unroll
    for (int im = 0; im < 2; im++)
        #pragma unroll
        for (int in = 0; in < 8; in++)
            #pragma unroll
            for (int j = 0; j < 4; j++) acc[im][in][j] = 0.0f;

    issue_stage(As[0], Bs[0], g_h3b, EB_LD, m0, g_eb, EB_LD, n0, 0, tid);
    cp_commit();
    const int NT = 19;
    for (int kt = 0; kt < NT; kt++) {
        if (kt + 1 < NT)
            issue_stage(As[(kt + 1) & 1], Bs[(kt + 1) & 1],
                        g_h3b, EB_LD, m0, g_eb, EB_LD, n0, (kt + 1) * 32, tid);
        cp_commit();
        cp_wait<1>();
        __syncthreads();
        compute_stage(As[kt & 1], Bs[kt & 1], wm, wn, lane, acc);
        __syncthreads();
    }
    #pragma unroll
    for (int im = 0; im < 2; im++) {
        int r = m0 + wm + im * 16 + gid;
        float hs0 = __ldg(&g_hsq[r]);
        float hs1 = __ldg(&g_hsq[r + 8]);
        #pragma unroll
        for (int in = 0; in < 8; in++) {
            int c = n0 + wn + in * 8 + tig * 2;
            if (c < NITEMS) {
                float e0 = __ldg(&g_esq[c]);
                float e1 = __ldg(&g_esq[c + 1]);
                float2 o0, o1;
                o0.x = hs0 + e0 - 2.0f * acc[im][in][0];
                o0.y = hs0 + e1 - 2.0f * acc[im][in][1];
                o1.x = hs1 + e0 - 2.0f * acc[im][in][2];
                o1.y = hs1 + e1 - 2.0f * acc[im][in][3];
                __stcs(reinterpret_cast<float2*>(&out[(size_t)r * NITEMS + c]), o0);
                __stcs(reinterpret_cast<float2*>(&out[(size_t)(r + 8) * NITEMS + c]), o1);
            }
        }
    }
}

// ---------------- launch ----------------
extern "C" void kernel_launch(void* const* d_in, const int* in_sizes, int n_in,
                              void* d_out, int out_size) {
    const float* x  = (const float*)d_in[0];
    const float* W1 = (const float*)d_in[1];
    const float* b1 = (const float*)d_in[2];
    const float* W2 = (const float*)d_in[3];
    const float* b2 = (const float*)d_in[4];
    const float* W3 = (const float*)d_in[5];
    const float* b3 = (const float*)d_in[6];
    const float* E  = (const float*)d_in[7];
    float* out = (float*)d_out;

    k_zero_h1pre<<<(B_ * H1 + 255) / 256, 256>>>();
    k_norm_convert<<<B_, 256>>>(x);
    k_prep_w1t<<<dim3((NITEMS + 31) / 32, (H1 + 31) / 32), 256>>>(W1);
    k_prep_eb<<<(NITEMS * (H1 / 4) + 255) / 256, 256>>>(E);
    k_esq<<<NITEMS / 8, 256>>>(E);
    k_gemm1<<<dim3(40, 23), 256>>>();
    k_act1<<<(B_ * H1 + 255) / 256, 256>>>(b1);
    k_mlp2<<<B_, 256>>>(W2, b2);
    k_mlp3<<<B_, 256>>>(W3, b3);
    k_gemm2<<<dim3(8, 391), 256>>>(out);
}